// round 4
// baseline (speedup 1.0000x reference)
#include <cuda_runtime.h>

#define NB 65536
#define NT 12
#define HD 128
#define G3 384
typedef unsigned long long ull;

// ---- scratch (device globals; no allocation allowed) ----
__device__ float g_h[3][NB][HD];       // GRU hidden states (enc, reused for dec)
__device__ float g_x[NB][HD];          // embedded encoder input
__device__ float g_r[NB][HD];          // rep (decoder initial carry)
__device__ float g_r2[NB][HD];         // relu(decoder in-projection)
__device__ float g_wt[6][256][G3];     // k-major GRU weights: rows 0..127 Wih^T, 128..255 Whh^T
__device__ float g_wt2[2][HD][HD];     // k-major enc_Wt, dec_Win

// ---- f32x2 helpers ----
__device__ __forceinline__ ull pack2(float a, float b) {
    ull r; asm("mov.b64 %0, {%1, %2};" : "=l"(r) : "f"(a), "f"(b)); return r;
}
__device__ __forceinline__ ull splat2(float a) {
    ull r; asm("mov.b64 %0, {%1, %1};" : "=l"(r) : "f"(a)); return r;
}
__device__ __forceinline__ void unpack2(ull v, float& a, float& b) {
    asm("mov.b64 {%0, %1}, %2;" : "=f"(a), "=f"(b) : "l"(v));
}
#define FMA2(acc, a, b) asm("fma.rn.f32x2 %0, %1, %2, %0;" : "+l"(acc) : "l"(a), "l"(b))

__device__ __forceinline__ float sigmoid_f(float x) {
    return __fdividef(1.0f, 1.0f + __expf(-x));
}
__device__ __forceinline__ float tanh_f(float x) {
    x = fminf(fmaxf(x, -9.0f), 9.0f);
    float e = __expf(2.0f * x);
    return __fdividef(e - 1.0f, e + 1.0f);
}

// ---- utility kernels ----
__global__ void k_clear_h() {
    size_t i = (size_t)blockIdx.x * 256 + threadIdx.x;
    ((float*)g_h)[i] = 0.0f;
}

// in: [G][K] row-major -> g_wt[wsel][roff + k][g]
__global__ void k_tr(const float* __restrict__ in, int wsel, int roff) {
    int i = blockIdx.x * 256 + threadIdx.x;
    if (i < G3 * HD) {
        int g = i / HD, k = i - g * HD;
        g_wt[wsel][roff + k][g] = in[i];
    }
}
// 128x128 transpose into g_wt2[sel]
__global__ void k_tr2(const float* __restrict__ in, int sel) {
    int i = blockIdx.x * 256 + threadIdx.x;
    int g = i >> 7, k = i & 127;
    g_wt2[sel][k][g] = in[i];
}

// g_x[b][e] = relu(x_true[b][t][:2] @ Wemb[e][:2] + bemb[e])
__global__ void k_embed(const float* __restrict__ x_true, const float* __restrict__ Wemb,
                        const float* __restrict__ bemb, int t) {
    int id = blockIdx.x * 256 + threadIdx.x;
    int e = id & (HD - 1), b = id >> 7;
    const float* x = x_true + ((size_t)b * NT + t) * 2;
    float v = fmaf(x[0], Wemb[2 * e], fmaf(x[1], Wemb[2 * e + 1], bemb[e]));
    g_x[b][e] = fmaxf(v, 0.0f);
}

// ---- fused GRU cell: H[row] <- GRUcell(X[row], H[row]) ----
// 64 rows/block: 8 warps x 8 rows/warp; lane owns gate pairs {2*lane + 64*m}.
__global__ void __launch_bounds__(256, 1)
k_gru(int xsel, int hsel, int wsel,
      const float* __restrict__ bih, const float* __restrict__ bhh) {
    const int warp = threadIdx.x >> 5, lane = threadIdx.x & 31;
    const int row0 = blockIdx.x * 64 + warp * 8;
    const float* Xb = (xsel == 0) ? &g_x[0][0] : (xsel == 3) ? &g_r2[0][0]
                                               : &g_h[xsel - 1][0][0];
    const float* __restrict__ Xp = Xb + (size_t)row0 * HD;
    float* __restrict__ Hp = &g_h[hsel][0][0] + (size_t)row0 * HD;
    const float* __restrict__ WT = &g_wt[wsel][0][0];
    const int g0 = 2 * lane;

    ull aRZ[8][4];   // r gates (m=0,1) + z gates (m=2,3)
    ull aNX[8][2];   // n gate, x contribution (+bih)
    ull aNH[8][2];   // n gate, h contribution (+bhh)

    #pragma unroll
    for (int m = 0; m < 4; m++) {
        int g = g0 + 64 * m;
        ull bv = pack2(bih[g] + bhh[g], bih[g + 1] + bhh[g + 1]);
        #pragma unroll
        for (int r = 0; r < 8; r++) aRZ[r][m] = bv;
    }
    #pragma unroll
    for (int q = 0; q < 2; q++) {
        int g = 256 + g0 + 64 * q;
        ull bx = pack2(bih[g], bih[g + 1]);
        ull bh = pack2(bhh[g], bhh[g + 1]);
        #pragma unroll
        for (int r = 0; r < 8; r++) { aNX[r][q] = bx; aNH[r][q] = bh; }
    }

    auto phase = [&](const float* __restrict__ A, const float* __restrict__ W,
                     ull (&aN)[8][2]) {
        #pragma unroll 1
        for (int k4 = 0; k4 < 32; k4++) {
            float4 a4[8];
            #pragma unroll
            for (int r = 0; r < 8; r++)
                a4[r] = *reinterpret_cast<const float4*>(A + r * HD + k4 * 4);
            #pragma unroll
            for (int c = 0; c < 4; c++) {
                const float* wr = W + (k4 * 4 + c) * G3;
                ull w[6];
                #pragma unroll
                for (int m = 0; m < 6; m++)
                    w[m] = *reinterpret_cast<const ull*>(wr + 64 * m);
                #pragma unroll
                for (int r = 0; r < 8; r++) {
                    float av = (c == 0) ? a4[r].x : (c == 1) ? a4[r].y
                             : (c == 2) ? a4[r].z : a4[r].w;
                    ull as = splat2(av);
                    FMA2(aRZ[r][0], as, w[0]);
                    FMA2(aRZ[r][1], as, w[1]);
                    FMA2(aRZ[r][2], as, w[2]);
                    FMA2(aRZ[r][3], as, w[3]);
                    FMA2(aN[r][0],  as, w[4]);
                    FMA2(aN[r][1],  as, w[5]);
                }
            }
        }
    };

    phase(Xp, WT + g0,            aNX);   // k in [0,128):   Wih^T
    phase(Hp, WT + 128 * G3 + g0, aNH);   // k in [128,256): Whh^T

    #pragma unroll
    for (int r = 0; r < 8; r++) {
        float* hrow = Hp + r * HD;
        #pragma unroll
        for (int q = 0; q < 2; q++) {
            int j = g0 + 64 * q;
            float r0, r1, z0, z1, nx0, nx1, nh0, nh1;
            unpack2(aRZ[r][q],     r0, r1);
            unpack2(aRZ[r][q + 2], z0, z1);
            unpack2(aNX[r][q],     nx0, nx1);
            unpack2(aNH[r][q],     nh0, nh1);
            float2 ho = *reinterpret_cast<const float2*>(hrow + j);
            float rr0 = sigmoid_f(r0), rr1 = sigmoid_f(r1);
            float zz0 = sigmoid_f(z0), zz1 = sigmoid_f(z1);
            float n0 = tanh_f(fmaf(rr0, nh0, nx0));
            float n1 = tanh_f(fmaf(rr1, nh1, nx1));
            float2 hn;
            hn.x = fmaf(zz0, ho.x - n0, n0);   // (1-z)*n + z*h
            hn.y = fmaf(zz1, ho.y - n1, n1);
            *reinterpret_cast<float2*>(hrow + j) = hn;
        }
    }
}

// ---- 128x128 dense (+bias, optional relu) ----
// isel: 0=g_r, 1=g_h[2].  osel: 0=g_r, 1=g_r2.
__global__ void __launch_bounds__(256, 2)
k_dense(int isel, int osel, int wsel, const float* __restrict__ bias, int relu) {
    const int warp = threadIdx.x >> 5, lane = threadIdx.x & 31;
    const int row0 = blockIdx.x * 64 + warp * 8;
    const float* __restrict__ Ap =
        ((isel == 0) ? &g_r[0][0] : &g_h[2][0][0]) + (size_t)row0 * HD;
    float* __restrict__ Op =
        ((osel == 0) ? &g_r[0][0] : &g_r2[0][0]) + (size_t)row0 * HD;
    const float* __restrict__ WT = &g_wt2[wsel][0][0];
    const int g0 = 2 * lane;

    ull acc[8][2];
    ull b0 = pack2(bias[g0], bias[g0 + 1]);
    ull b1 = pack2(bias[g0 + 64], bias[g0 + 65]);
    #pragma unroll
    for (int r = 0; r < 8; r++) { acc[r][0] = b0; acc[r][1] = b1; }

    #pragma unroll 1
    for (int k4 = 0; k4 < 32; k4++) {
        float4 a4[8];
        #pragma unroll
        for (int r = 0; r < 8; r++)
            a4[r] = *reinterpret_cast<const float4*>(Ap + r * HD + k4 * 4);
        #pragma unroll
        for (int c = 0; c < 4; c++) {
            const float* wr = WT + (k4 * 4 + c) * HD + g0;
            ull w0 = *reinterpret_cast<const ull*>(wr);
            ull w1 = *reinterpret_cast<const ull*>(wr + 64);
            #pragma unroll
            for (int r = 0; r < 8; r++) {
                float av = (c == 0) ? a4[r].x : (c == 1) ? a4[r].y
                         : (c == 2) ? a4[r].z : a4[r].w;
                ull as = splat2(av);
                FMA2(acc[r][0], as, w0);
                FMA2(acc[r][1], as, w1);
            }
        }
    }

    #pragma unroll
    for (int r = 0; r < 8; r++) {
        #pragma unroll
        for (int m = 0; m < 2; m++) {
            float v0, v1;
            unpack2(acc[r][m], v0, v1);
            if (relu) { v0 = fmaxf(v0, 0.0f); v1 = fmaxf(v1, 0.0f); }
            *reinterpret_cast<float2*>(Op + r * HD + g0 + 64 * m) =
                make_float2(v0, v1);
        }
    }
}

// ---- output head: y[b][t][:] = g_h[2][b] @ Wout.T + bout ----
__global__ void k_out(const float* __restrict__ Wout, const float* __restrict__ bout,
                      float* __restrict__ out, int t) {
    int warp = threadIdx.x >> 5, lane = threadIdx.x & 31;
    int b = blockIdx.x * 8 + warp;
    const float* h = &g_h[2][b][0];
    float4 hv = *reinterpret_cast<const float4*>(h + lane * 4);
    float4 w0 = *reinterpret_cast<const float4*>(Wout + lane * 4);
    float4 w1 = *reinterpret_cast<const float4*>(Wout + HD + lane * 4);
    float d0 = hv.x * w0.x + hv.y * w0.y + hv.z * w0.z + hv.w * w0.w;
    float d1 = hv.x * w1.x + hv.y * w1.y + hv.z * w1.z + hv.w * w1.w;
    #pragma unroll
    for (int s = 16; s; s >>= 1) {
        d0 += __shfl_xor_sync(0xFFFFFFFFu, d0, s);
        d1 += __shfl_xor_sync(0xFFFFFFFFu, d1, s);
    }
    if (lane == 0) {
        float* o = out + ((size_t)b * NT + t) * 2;
        o[0] = d0 + bout[0];
        o[1] = d1 + bout[1];
    }
}

extern "C" void kernel_launch(void* const* d_in, const int* in_sizes, int n_in,
                              void* d_out, int out_size) {
    const float* x_true   = (const float*)d_in[0];
    const float* enc_Wemb = (const float*)d_in[1];
    const float* enc_bemb = (const float*)d_in[2];
    const float* enc_Wih  = (const float*)d_in[3];
    const float* enc_Whh  = (const float*)d_in[4];
    const float* enc_bih  = (const float*)d_in[5];
    const float* enc_bhh  = (const float*)d_in[6];
    const float* enc_Wt   = (const float*)d_in[7];
    const float* enc_bt   = (const float*)d_in[8];
    const float* dec_Win  = (const float*)d_in[9];
    const float* dec_bin  = (const float*)d_in[10];
    const float* dec_Wih  = (const float*)d_in[11];
    const float* dec_Whh  = (const float*)d_in[12];
    const float* dec_bih  = (const float*)d_in[13];
    const float* dec_bhh  = (const float*)d_in[14];
    const float* dec_Wout = (const float*)d_in[15];
    const float* dec_bout = (const float*)d_in[16];
    float* out = (float*)d_out;

    const int trB = (G3 * HD + 255) / 256;
    for (int l = 0; l < 3; l++) {
        k_tr<<<trB, 256>>>(enc_Wih + (size_t)l * G3 * HD, l, 0);
        k_tr<<<trB, 256>>>(enc_Whh + (size_t)l * G3 * HD, l, 128);
        k_tr<<<trB, 256>>>(dec_Wih + (size_t)l * G3 * HD, 3 + l, 0);
        k_tr<<<trB, 256>>>(dec_Whh + (size_t)l * G3 * HD, 3 + l, 128);
    }
    k_tr2<<<64, 256>>>(enc_Wt, 0);
    k_tr2<<<64, 256>>>(dec_Win, 1);
    k_clear_h<<<3 * NB * HD / 256, 256>>>();

    // ---- encoder: steps 1..T-2, 3-layer stack (step 0 discarded per reference) ----
    for (int t = 1; t <= NT - 2; t++) {
        k_embed<<<NB * HD / 256, 256>>>(x_true, enc_Wemb, enc_bemb, t);
        k_gru<<<NB / 64, 256>>>(0, 0, 0, enc_bih,          enc_bhh);
        k_gru<<<NB / 64, 256>>>(1, 1, 1, enc_bih + G3,     enc_bhh + G3);
        k_gru<<<NB / 64, 256>>>(2, 2, 2, enc_bih + 2 * G3, enc_bhh + 2 * G3);
    }
    // rep = g_h[2] @ enc_Wt^T + enc_bt  -> g_r
    k_dense<<<NB / 64, 256>>>(1, 0, 0, enc_bt, 0);
    k_clear_h<<<3 * NB * HD / 256, 256>>>();

    // ---- decoder: 12 steps; carry r = top-layer hidden (g_h[2]) ----
    for (int i = 0; i < NT; i++) {
        k_dense<<<NB / 64, 256>>>(i == 0 ? 0 : 1, 1, 1, dec_bin, 1);  // relu proj -> g_r2
        k_gru<<<NB / 64, 256>>>(3, 0, 3, dec_bih,          dec_bhh);
        k_gru<<<NB / 64, 256>>>(1, 1, 4, dec_bih + G3,     dec_bhh + G3);
        k_gru<<<NB / 64, 256>>>(2, 2, 5, dec_bih + 2 * G3, dec_bhh + 2 * G3);
        k_out<<<NB / 8, 256>>>(dec_Wout, dec_bout, out, i);
    }
}

// round 6
// speedup vs baseline: 2.8793x; 2.8793x over previous
#include <cuda_runtime.h>
#include <cstdint>

#define NB 65536
#define NT 12
#define HD 128
#define G3 384
typedef unsigned long long ull;

// ---- scratch (device globals; no allocation allowed) ----
__device__ float g_h[3][NB][HD];        // GRU hidden states
__device__ float g_x[NB][HD];           // embedded encoder input
__device__ float g_r[NB][HD];           // rep (decoder initial carry)
__device__ float g_r2[NB][HD];          // relu(decoder in-projection)
// Pre-packed tf32 weights, mma-fragment order.
// Per cell: 6 jobs [r_x, r_h, z_x, z_h, n_x, n_h], each 16 kt x 16 nt tiles,
// each tile = 32 lanes x 2 floats: (W[n][k], W[n][k+4]).
__device__ float g_wB[6][6 * 16 * 16 * 64];
__device__ float g_wt2[2][HD][HD];      // k-major enc_Wt, dec_Win (SIMT dense)

// ================= helpers =================
__device__ __forceinline__ float tf32r(float v) {
    uint32_t u; asm("cvt.rna.tf32.f32 %0, %1;" : "=r"(u) : "f"(v));
    return __uint_as_float(u);
}
__device__ __forceinline__ float sigmoid_f(float x) {
    return __fdividef(1.0f, 1.0f + __expf(-x));
}
__device__ __forceinline__ float tanh_f(float x) {
    x = fminf(fmaxf(x, -9.0f), 9.0f);
    float e = __expf(2.0f * x);
    return __fdividef(e - 1.0f, e + 1.0f);
}
// ---- f32x2 helpers (SIMT dense path) ----
__device__ __forceinline__ ull pack2(float a, float b) {
    ull r; asm("mov.b64 %0, {%1, %2};" : "=l"(r) : "f"(a), "f"(b)); return r;
}
__device__ __forceinline__ ull splat2(float a) {
    ull r; asm("mov.b64 %0, {%1, %1};" : "=l"(r) : "f"(a)); return r;
}
__device__ __forceinline__ void unpack2(ull v, float& a, float& b) {
    asm("mov.b64 {%0, %1}, %2;" : "=f"(a), "=f"(b) : "l"(v));
}
#define FMA2(acc, a, b) asm("fma.rn.f32x2 %0, %1, %2, %0;" : "+l"(acc) : "l"(a), "l"(b))

// ================= utility kernels =================
__global__ void k_clear_h() {
    size_t i = (size_t)blockIdx.x * 256 + threadIdx.x;
    ((float*)g_h)[i] = 0.0f;
}

// Pre-pack tf32 weights for one cell into mma-fragment order.
// i -> (j, kt, nt, lane); writes float2 pair (W[n][k], W[n][k+4]).
__global__ void k_prepw(const float* __restrict__ Wih, const float* __restrict__ Whh, int wsel) {
    int i = blockIdx.x * 256 + threadIdx.x;      // 49152 pairs
    if (i >= 6 * 16 * 16 * 32) return;
    int lane = i & 31;
    int nt = (i >> 5) & 15;
    int kt = (i >> 9) & 15;
    int j  = i >> 13;                            // 0..5
    const float* W = (j & 1) ? Whh : Wih;
    int gbase = (j >> 1) * 128;                  // 0: r, 1: z, 2: n
    int n = nt * 8 + (lane >> 2);
    int k = kt * 8 + (lane & 3);
    const float* src = W + (size_t)(gbase + n) * HD + k;
    float v0 = tf32r(src[0]);
    float v1 = tf32r(src[4]);
    *reinterpret_cast<float2*>(&g_wB[wsel][((j * 256 + kt * 16 + nt) * 64) + lane * 2]) =
        make_float2(v0, v1);
}

// 128x128 transpose into g_wt2[sel]
__global__ void k_tr2(const float* __restrict__ in, int sel) {
    int i = blockIdx.x * 256 + threadIdx.x;
    int g = i >> 7, k = i & 127;
    g_wt2[sel][k][g] = in[i];
}

// g_x[b][e] = relu(x_true[b][t][:2] @ Wemb[e][:2] + bemb[e])
__global__ void k_embed(const float* __restrict__ x_true, const float* __restrict__ Wemb,
                        const float* __restrict__ bemb, int t) {
    int id = blockIdx.x * 256 + threadIdx.x;
    int e = id & (HD - 1), b = id >> 7;
    const float* x = x_true + ((size_t)b * NT + t) * 2;
    float v = fmaf(x[0], Wemb[2 * e], fmaf(x[1], Wemb[2 * e + 1], bemb[e]));
    g_x[b][e] = fmaxf(v, 0.0f);
}

// ================= tensor-core (mma.sync tf32) GRU cell =================
// CTA: 64 rows, 256 threads = 8 warps in 2(m) x 4(n) grid; warp tile 32x32.
// SMEM: A0 = X tile, A1 = H tile, each 64 x 132 floats (pad 4) = 33792 B.
#define APAD 132
#define SMEM_GRU (2 * 64 * APAD * 4)

// one 64x128x128 pass: acc += A(smem) * Bjob^T
__device__ __forceinline__ void gemm64(float (&acc)[2][4][4], const float* __restrict__ As,
                                       const float* __restrict__ Bj,
                                       int warpm, int warpn, int g, int t4, int lane) {
    #pragma unroll 2
    for (int kt = 0; kt < 16; kt++) {
        uint32_t a[2][4];
        #pragma unroll
        for (int mt = 0; mt < 2; mt++) {
            const float* ap = As + (warpm * 32 + mt * 16 + g) * APAD + kt * 8 + t4;
            a[mt][0] = __float_as_uint(ap[0]);
            a[mt][1] = __float_as_uint(ap[8 * APAD]);
            a[mt][2] = __float_as_uint(ap[4]);
            a[mt][3] = __float_as_uint(ap[8 * APAD + 4]);
        }
        #pragma unroll
        for (int nt = 0; nt < 4; nt++) {
            float2 bv = *reinterpret_cast<const float2*>(
                Bj + (kt * 16 + warpn * 4 + nt) * 64 + lane * 2);
            uint32_t b0 = __float_as_uint(bv.x), b1 = __float_as_uint(bv.y);
            #pragma unroll
            for (int mt = 0; mt < 2; mt++) {
                asm volatile(
                    "mma.sync.aligned.m16n8k8.row.col.f32.tf32.tf32.f32 "
                    "{%0,%1,%2,%3}, {%4,%5,%6,%7}, {%8,%9}, {%0,%1,%2,%3};"
                    : "+f"(acc[mt][nt][0]), "+f"(acc[mt][nt][1]),
                      "+f"(acc[mt][nt][2]), "+f"(acc[mt][nt][3])
                    : "r"(a[mt][0]), "r"(a[mt][1]), "r"(a[mt][2]), "r"(a[mt][3]),
                      "r"(b0), "r"(b1));
            }
        }
    }
}
#define ZERO_ACC(A) { _Pragma("unroll") for (int _m = 0; _m < 2; _m++) \
    _Pragma("unroll") for (int _n = 0; _n < 4; _n++) \
    _Pragma("unroll") for (int _e = 0; _e < 4; _e++) (A)[_m][_n][_e] = 0.0f; }

__global__ void __launch_bounds__(256, 2)
k_gru_mma(int xsel, int hsel, int wsel,
          const float* __restrict__ bih, const float* __restrict__ bhh) {
    extern __shared__ float As[];                 // [2][64][APAD]
    float* A0 = As;
    float* A1 = As + 64 * APAD;
    const int tid = threadIdx.x, wid = tid >> 5, lane = tid & 31;
    const int warpm = wid >> 2, warpn = wid & 3;
    const int g = lane >> 2, t4 = lane & 3;
    const int row0 = blockIdx.x * 64;

    const float* X = (xsel == 0) ? &g_x[0][0] : (xsel == 3) ? &g_r2[0][0]
                                              : &g_h[xsel - 1][0][0];
    const float* __restrict__ Xt = X + (size_t)row0 * HD;
    float* __restrict__ Ht = &g_h[hsel][0][0] + (size_t)row0 * HD;
    const float* __restrict__ WB = &g_wB[wsel][0];

    // load X -> A0, H -> A1 (tf32-rounded, padded, 16B-aligned v4 stores)
    #pragma unroll
    for (int i = tid; i < 64 * 32; i += 256) {
        int r = i >> 5, c4 = i & 31;
        float4 v = *reinterpret_cast<const float4*>(Xt + r * HD + c4 * 4);
        v.x = tf32r(v.x); v.y = tf32r(v.y); v.z = tf32r(v.z); v.w = tf32r(v.w);
        *reinterpret_cast<float4*>(A0 + r * APAD + c4 * 4) = v;
    }
    #pragma unroll
    for (int i = tid; i < 64 * 32; i += 256) {
        int r = i >> 5, c4 = i & 31;
        float4 v = *reinterpret_cast<const float4*>(Ht + r * HD + c4 * 4);
        v.x = tf32r(v.x); v.y = tf32r(v.y); v.z = tf32r(v.z); v.w = tf32r(v.w);
        *reinterpret_cast<float4*>(A1 + r * APAD + c4 * 4) = v;
    }
    __syncthreads();

    float accU[2][4][4], accV[2][4][4];

    // r = sigmoid(X Wr_x^T + H Wr_h^T + bih_r + bhh_r)   -> accU
    ZERO_ACC(accU);
    gemm64(accU, A0, WB + 0 * 16384, warpm, warpn, g, t4, lane);
    gemm64(accU, A1, WB + 1 * 16384, warpm, warpn, g, t4, lane);
    #pragma unroll
    for (int mt = 0; mt < 2; mt++)
        #pragma unroll
        for (int nt = 0; nt < 4; nt++) {
            int col = warpn * 32 + nt * 8 + t4 * 2;
            float b0 = bih[col] + bhh[col], b1 = bih[col + 1] + bhh[col + 1];
            accU[mt][nt][0] = sigmoid_f(accU[mt][nt][0] + b0);
            accU[mt][nt][1] = sigmoid_f(accU[mt][nt][1] + b1);
            accU[mt][nt][2] = sigmoid_f(accU[mt][nt][2] + b0);
            accU[mt][nt][3] = sigmoid_f(accU[mt][nt][3] + b1);
        }

    // accU = r * (H Wn_h^T + bhh_n)
    ZERO_ACC(accV);
    gemm64(accV, A1, WB + 5 * 16384, warpm, warpn, g, t4, lane);
    #pragma unroll
    for (int mt = 0; mt < 2; mt++)
        #pragma unroll
        for (int nt = 0; nt < 4; nt++) {
            int col = 256 + warpn * 32 + nt * 8 + t4 * 2;
            float b0 = bhh[col], b1 = bhh[col + 1];
            accU[mt][nt][0] *= accV[mt][nt][0] + b0;
            accU[mt][nt][1] *= accV[mt][nt][1] + b1;
            accU[mt][nt][2] *= accV[mt][nt][2] + b0;
            accU[mt][nt][3] *= accV[mt][nt][3] + b1;
        }

    // n = tanh(X Wn_x^T + bih_n + accU)   -> accU
    ZERO_ACC(accV);
    gemm64(accV, A0, WB + 4 * 16384, warpm, warpn, g, t4, lane);
    #pragma unroll
    for (int mt = 0; mt < 2; mt++)
        #pragma unroll
        for (int nt = 0; nt < 4; nt++) {
            int col = 256 + warpn * 32 + nt * 8 + t4 * 2;
            float b0 = bih[col], b1 = bih[col + 1];
            accU[mt][nt][0] = tanh_f(accV[mt][nt][0] + b0 + accU[mt][nt][0]);
            accU[mt][nt][1] = tanh_f(accV[mt][nt][1] + b1 + accU[mt][nt][1]);
            accU[mt][nt][2] = tanh_f(accV[mt][nt][2] + b0 + accU[mt][nt][2]);
            accU[mt][nt][3] = tanh_f(accV[mt][nt][3] + b1 + accU[mt][nt][3]);
        }

    // z = sigmoid(X Wz_x^T + H Wz_h^T + b)  -> accV; h' = n + z*(h_old - n)
    ZERO_ACC(accV);
    gemm64(accV, A0, WB + 2 * 16384, warpm, warpn, g, t4, lane);
    gemm64(accV, A1, WB + 3 * 16384, warpm, warpn, g, t4, lane);
    #pragma unroll
    for (int mt = 0; mt < 2; mt++)
        #pragma unroll
        for (int nt = 0; nt < 4; nt++) {
            int col = warpn * 32 + nt * 8 + t4 * 2;
            float b0 = bih[128 + col] + bhh[128 + col];
            float b1 = bih[129 + col] + bhh[129 + col];
            int r0 = warpm * 32 + mt * 16 + g;
            float2 ho0 = *reinterpret_cast<const float2*>(Ht + r0 * HD + col);
            float2 ho1 = *reinterpret_cast<const float2*>(Ht + (r0 + 8) * HD + col);
            float z0 = sigmoid_f(accV[mt][nt][0] + b0);
            float z1 = sigmoid_f(accV[mt][nt][1] + b1);
            float z2 = sigmoid_f(accV[mt][nt][2] + b0);
            float z3 = sigmoid_f(accV[mt][nt][3] + b1);
            float2 o0, o1;
            o0.x = fmaf(z0, ho0.x - accU[mt][nt][0], accU[mt][nt][0]);
            o0.y = fmaf(z1, ho0.y - accU[mt][nt][1], accU[mt][nt][1]);
            o1.x = fmaf(z2, ho1.x - accU[mt][nt][2], accU[mt][nt][2]);
            o1.y = fmaf(z3, ho1.y - accU[mt][nt][3], accU[mt][nt][3]);
            *reinterpret_cast<float2*>(Ht + r0 * HD + col) = o0;
            *reinterpret_cast<float2*>(Ht + (r0 + 8) * HD + col) = o1;
        }
}

// ================= SIMT 128x128 dense (+bias, optional relu) =================
__global__ void __launch_bounds__(256, 2)
k_dense(int isel, int osel, int wsel, const float* __restrict__ bias, int relu) {
    const int warp = threadIdx.x >> 5, lane = threadIdx.x & 31;
    const int row0 = blockIdx.x * 64 + warp * 8;
    const float* __restrict__ Ap =
        ((isel == 0) ? &g_r[0][0] : &g_h[2][0][0]) + (size_t)row0 * HD;
    float* __restrict__ Op =
        ((osel == 0) ? &g_r[0][0] : &g_r2[0][0]) + (size_t)row0 * HD;
    const float* __restrict__ WT = &g_wt2[wsel][0][0];
    const int g0 = 2 * lane;

    ull acc[8][2];
    ull b0 = pack2(bias[g0], bias[g0 + 1]);
    ull b1 = pack2(bias[g0 + 64], bias[g0 + 65]);
    #pragma unroll
    for (int r = 0; r < 8; r++) { acc[r][0] = b0; acc[r][1] = b1; }

    #pragma unroll 1
    for (int k4 = 0; k4 < 32; k4++) {
        float4 a4[8];
        #pragma unroll
        for (int r = 0; r < 8; r++)
            a4[r] = *reinterpret_cast<const float4*>(Ap + r * HD + k4 * 4);
        #pragma unroll
        for (int c = 0; c < 4; c++) {
            const float* wr = WT + (k4 * 4 + c) * HD + g0;
            ull w0 = *reinterpret_cast<const ull*>(wr);
            ull w1 = *reinterpret_cast<const ull*>(wr + 64);
            #pragma unroll
            for (int r = 0; r < 8; r++) {
                float av = (c == 0) ? a4[r].x : (c == 1) ? a4[r].y
                         : (c == 2) ? a4[r].z : a4[r].w;
                ull as = splat2(av);
                FMA2(acc[r][0], as, w0);
                FMA2(acc[r][1], as, w1);
            }
        }
    }
    #pragma unroll
    for (int r = 0; r < 8; r++) {
        #pragma unroll
        for (int m = 0; m < 2; m++) {
            float v0, v1;
            unpack2(acc[r][m], v0, v1);
            if (relu) { v0 = fmaxf(v0, 0.0f); v1 = fmaxf(v1, 0.0f); }
            *reinterpret_cast<float2*>(Op + r * HD + g0 + 64 * m) = make_float2(v0, v1);
        }
    }
}

// ---- output head: y[b][t][:] = g_h[2][b] @ Wout.T + bout ----
__global__ void k_out(const float* __restrict__ Wout, const float* __restrict__ bout,
                      float* __restrict__ out, int t) {
    int warp = threadIdx.x >> 5, lane = threadIdx.x & 31;
    int b = blockIdx.x * 8 + warp;
    const float* h = &g_h[2][b][0];
    float4 hv = *reinterpret_cast<const float4*>(h + lane * 4);
    float4 w0 = *reinterpret_cast<const float4*>(Wout + lane * 4);
    float4 w1 = *reinterpret_cast<const float4*>(Wout + HD + lane * 4);
    float d0 = hv.x * w0.x + hv.y * w0.y + hv.z * w0.z + hv.w * w0.w;
    float d1 = hv.x * w1.x + hv.y * w1.y + hv.z * w1.z + hv.w * w1.w;
    #pragma unroll
    for (int s = 16; s; s >>= 1) {
        d0 += __shfl_xor_sync(0xFFFFFFFFu, d0, s);
        d1 += __shfl_xor_sync(0xFFFFFFFFu, d1, s);
    }
    if (lane == 0) {
        float* o = out + ((size_t)b * NT + t) * 2;
        o[0] = d0 + bout[0];
        o[1] = d1 + bout[1];
    }
}

extern "C" void kernel_launch(void* const* d_in, const int* in_sizes, int n_in,
                              void* d_out, int out_size) {
    const float* x_true   = (const float*)d_in[0];
    const float* enc_Wemb = (const float*)d_in[1];
    const float* enc_bemb = (const float*)d_in[2];
    const float* enc_Wih  = (const float*)d_in[3];
    const float* enc_Whh  = (const float*)d_in[4];
    const float* enc_bih  = (const float*)d_in[5];
    const float* enc_bhh  = (const float*)d_in[6];
    const float* enc_Wt   = (const float*)d_in[7];
    const float* enc_bt   = (const float*)d_in[8];
    const float* dec_Win  = (const float*)d_in[9];
    const float* dec_bin  = (const float*)d_in[10];
    const float* dec_Wih  = (const float*)d_in[11];
    const float* dec_Whh  = (const float*)d_in[12];
    const float* dec_bih  = (const float*)d_in[13];
    const float* dec_bhh  = (const float*)d_in[14];
    const float* dec_Wout = (const float*)d_in[15];
    const float* dec_bout = (const float*)d_in[16];
    float* out = (float*)d_out;

    cudaFuncSetAttribute(k_gru_mma, cudaFuncAttributeMaxDynamicSharedMemorySize, SMEM_GRU);

    for (int l = 0; l < 3; l++) {
        k_prepw<<<192, 256>>>(enc_Wih + (size_t)l * G3 * HD, enc_Whh + (size_t)l * G3 * HD, l);
        k_prepw<<<192, 256>>>(dec_Wih + (size_t)l * G3 * HD, dec_Whh + (size_t)l * G3 * HD, 3 + l);
    }
    k_tr2<<<64, 256>>>(enc_Wt, 0);
    k_tr2<<<64, 256>>>(dec_Win, 1);
    k_clear_h<<<3 * NB * HD / 256, 256>>>();

    // ---- encoder: steps 1..T-2 (step 0 discarded per reference) ----
    for (int t = 1; t <= NT - 2; t++) {
        k_embed<<<NB * HD / 256, 256>>>(x_true, enc_Wemb, enc_bemb, t);
        k_gru_mma<<<NB / 64, 256, SMEM_GRU>>>(0, 0, 0, enc_bih,          enc_bhh);
        k_gru_mma<<<NB / 64, 256, SMEM_GRU>>>(1, 1, 1, enc_bih + G3,     enc_bhh + G3);
        k_gru_mma<<<NB / 64, 256, SMEM_GRU>>>(2, 2, 2, enc_bih + 2 * G3, enc_bhh + 2 * G3);
    }
    k_dense<<<NB / 64, 256>>>(1, 0, 0, enc_bt, 0);   // rep = h_top @ enc_Wt^T + bt -> g_r
    k_clear_h<<<3 * NB * HD / 256, 256>>>();

    // ---- decoder: 12 steps; carry r = top-layer hidden ----
    for (int i = 0; i < NT; i++) {
        k_dense<<<NB / 64, 256>>>(i == 0 ? 0 : 1, 1, 1, dec_bin, 1);   // relu proj -> g_r2
        k_gru_mma<<<NB / 64, 256, SMEM_GRU>>>(3, 0, 3, dec_bih,          dec_bhh);
        k_gru_mma<<<NB / 64, 256, SMEM_GRU>>>(1, 1, 4, dec_bih + G3,     dec_bhh + G3);
        k_gru_mma<<<NB / 64, 256, SMEM_GRU>>>(2, 2, 5, dec_bih + 2 * G3, dec_bhh + 2 * G3);
        k_out<<<NB / 8, 256>>>(dec_Wout, dec_bout, out, i);
    }
}

// round 7
// speedup vs baseline: 3.1166x; 1.0824x over previous
#include <cuda_runtime.h>
#include <cstdint>

#define NB 65536
#define NT 12
#define HD 128
#define G3 384
#define ROWS 32
#define APAD 132
#define SMEM_NET (4 * ROWS * APAD * 4)   // 67584 B: he0,he1,he2,xe
typedef unsigned long long ull;

// ---- device scratch (no allocation allowed) ----
// Pre-packed tf32 weights, mma-fragment order. Per cell: 6 jobs
// [r_x, r_h, z_x, z_h, n_x, n_h], each 16kt x 16nt tiles of 64 floats.
__device__ float g_wB[6][6 * 16384];
__device__ float g_wt2[2][HD][HD];      // k-major enc_Wt, dec_Win (SIMT dense)

// ================= helpers =================
__device__ __forceinline__ uint32_t smem_u32(const void* p) {
    uint32_t a;
    asm("{ .reg .u64 t; cvta.to.shared.u64 t, %1; cvt.u32.u64 %0, t; }" : "=r"(a) : "l"(p));
    return a;
}
__device__ __forceinline__ uint32_t tf32b(float v) {
    uint32_t u; asm("cvt.rna.tf32.f32 %0, %1;" : "=r"(u) : "f"(v));
    return u;
}
__device__ __forceinline__ float sigmoid_f(float x) {
    return __fdividef(1.0f, 1.0f + __expf(-x));
}
__device__ __forceinline__ float tanh_f(float x) {
    x = fminf(fmaxf(x, -9.0f), 9.0f);
    float e = __expf(2.0f * x);
    return __fdividef(e - 1.0f, e + 1.0f);
}
__device__ __forceinline__ ull pack2(float a, float b) {
    ull r; asm("mov.b64 %0, {%1, %2};" : "=l"(r) : "f"(a), "f"(b)); return r;
}
__device__ __forceinline__ ull splat2(float a) {
    ull r; asm("mov.b64 %0, {%1, %1};" : "=l"(r) : "f"(a)); return r;
}
__device__ __forceinline__ void unpack2(ull v, float& a, float& b) {
    asm("mov.b64 {%0, %1}, %2;" : "=f"(a), "=f"(b) : "l"(v));
}
#define FMA2(acc, a, b) asm("fma.rn.f32x2 %0, %1, %2, %0;" : "+l"(acc) : "l"(a), "l"(b))

__device__ __forceinline__ float lds1(uint32_t a) {
    float v; asm volatile("ld.shared.b32 %0, [%1];" : "=f"(v) : "r"(a)); return v;
}
__device__ __forceinline__ float2 lds2(uint32_t a) {
    float2 v; asm volatile("ld.shared.v2.f32 {%0,%1}, [%2];" : "=f"(v.x), "=f"(v.y) : "r"(a));
    return v;
}
__device__ __forceinline__ float4 lds4(uint32_t a) {
    float4 v;
    asm volatile("ld.shared.v4.f32 {%0,%1,%2,%3}, [%4];"
                 : "=f"(v.x), "=f"(v.y), "=f"(v.z), "=f"(v.w) : "r"(a));
    return v;
}
__device__ __forceinline__ void sts2(uint32_t a, float2 v) {
    asm volatile("st.shared.v2.f32 [%0], {%1,%2};" :: "r"(a), "f"(v.x), "f"(v.y) : "memory");
}

// ================= prep kernels =================
// Pack all 6 GRU cells' weights into mma-fragment order (tf32-rounded).
__global__ void k_prep_all(const float* __restrict__ eWih, const float* __restrict__ eWhh,
                           const float* __restrict__ dWih, const float* __restrict__ dWhh) {
    int wsel = blockIdx.x / 192;
    int i = (blockIdx.x % 192) * 256 + threadIdx.x;     // 49152 pairs per cell
    int l = wsel % 3;
    const float* Wih = (wsel < 3 ? eWih : dWih) + (size_t)l * G3 * HD;
    const float* Whh = (wsel < 3 ? eWhh : dWhh) + (size_t)l * G3 * HD;
    int lane = i & 31;
    int nt = (i >> 5) & 15;
    int kt = (i >> 9) & 15;
    int j  = i >> 13;                                   // 0..5
    const float* W = (j & 1) ? Whh : Wih;
    int gbase = (j >> 1) * 128;                         // 0:r 1:z 2:n
    int n = nt * 8 + (lane >> 2);
    int k = kt * 8 + (lane & 3);
    const float* src = W + (size_t)(gbase + n) * HD + k;
    float v0 = __uint_as_float(tf32b(src[0]));
    float v1 = __uint_as_float(tf32b(src[4]));
    *reinterpret_cast<float2*>(&g_wB[wsel][((j * 256 + kt * 16 + nt) * 64) + lane * 2]) =
        make_float2(v0, v1);
}

// k-major transposes of enc_Wt / dec_Win (exact fp32, SIMT dense path)
__global__ void k_tr2_all(const float* __restrict__ enc_Wt, const float* __restrict__ dec_Win) {
    int sel = blockIdx.x >> 6;
    int i = (blockIdx.x & 63) * 256 + threadIdx.x;
    const float* in = sel ? dec_Win : enc_Wt;
    g_wt2[sel][i & 127][i >> 7] = in[i];
}

// ================= fused GRU cell (SMEM-resident, one code copy) =================
// 32 rows, 8 warps in 2(m) x 4(n); warp tile 16 x 32.
__device__ __noinline__ void cellf(uint32_t xs, uint32_t hs,
                                   const float* __restrict__ WB,
                                   const float* __restrict__ bih,
                                   const float* __restrict__ bhh) {
    const int tid = threadIdx.x, wid = tid >> 5, lane = tid & 31;
    const int warpm = wid >> 2, warpn = wid & 3;
    const int g = lane >> 2, t4 = lane & 3;
    const uint32_t arow = (uint32_t)(warpm * 16 + g) * (APAD * 4);
    float accU[4][4], accV[4][4];

    auto gemm = [&](float (&acc)[4][4], uint32_t As, const float* __restrict__ Bj) {
        const uint32_t ab = As + arow + t4 * 4;
        #pragma unroll 4
        for (int kt = 0; kt < 16; kt++) {
            uint32_t ap = ab + kt * 32;
            uint32_t a0 = tf32b(lds1(ap));
            uint32_t a1 = tf32b(lds1(ap + 8 * APAD * 4));
            uint32_t a2 = tf32b(lds1(ap + 16));
            uint32_t a3 = tf32b(lds1(ap + 8 * APAD * 4 + 16));
            const float* bp = Bj + (kt * 16 + warpn * 4) * 64 + lane * 2;
            #pragma unroll
            for (int nt = 0; nt < 4; nt++) {
                float2 bv = *reinterpret_cast<const float2*>(bp + nt * 64);
                asm volatile(
                    "mma.sync.aligned.m16n8k8.row.col.f32.tf32.tf32.f32 "
                    "{%0,%1,%2,%3}, {%4,%5,%6,%7}, {%8,%9}, {%0,%1,%2,%3};"
                    : "+f"(acc[nt][0]), "+f"(acc[nt][1]), "+f"(acc[nt][2]), "+f"(acc[nt][3])
                    : "r"(a0), "r"(a1), "r"(a2), "r"(a3),
                      "r"(__float_as_uint(bv.x)), "r"(__float_as_uint(bv.y)));
            }
        }
    };
    #define ZACC(A) { _Pragma("unroll") for (int _n = 0; _n < 4; _n++) \
        _Pragma("unroll") for (int _e = 0; _e < 4; _e++) (A)[_n][_e] = 0.0f; }

    // r = sigmoid(x Wr_x^T + h Wr_h^T + b)
    ZACC(accU);
    gemm(accU, xs, WB + 0 * 16384);
    gemm(accU, hs, WB + 1 * 16384);
    #pragma unroll
    for (int nt = 0; nt < 4; nt++) {
        int col = warpn * 32 + nt * 8 + t4 * 2;
        float b0 = bih[col] + bhh[col], b1 = bih[col + 1] + bhh[col + 1];
        accU[nt][0] = sigmoid_f(accU[nt][0] + b0);
        accU[nt][1] = sigmoid_f(accU[nt][1] + b1);
        accU[nt][2] = sigmoid_f(accU[nt][2] + b0);
        accU[nt][3] = sigmoid_f(accU[nt][3] + b1);
    }
    // accU = r * (h Wn_h^T + bhh_n)
    ZACC(accV);
    gemm(accV, hs, WB + 5 * 16384);
    #pragma unroll
    for (int nt = 0; nt < 4; nt++) {
        int col = 256 + warpn * 32 + nt * 8 + t4 * 2;
        float b0 = bhh[col], b1 = bhh[col + 1];
        accU[nt][0] *= accV[nt][0] + b0;
        accU[nt][1] *= accV[nt][1] + b1;
        accU[nt][2] *= accV[nt][2] + b0;
        accU[nt][3] *= accV[nt][3] + b1;
    }
    // n = tanh(x Wn_x^T + bih_n + accU)
    ZACC(accV);
    gemm(accV, xs, WB + 4 * 16384);
    #pragma unroll
    for (int nt = 0; nt < 4; nt++) {
        int col = 256 + warpn * 32 + nt * 8 + t4 * 2;
        float b0 = bih[col], b1 = bih[col + 1];
        accU[nt][0] = tanh_f(accV[nt][0] + b0 + accU[nt][0]);
        accU[nt][1] = tanh_f(accV[nt][1] + b1 + accU[nt][1]);
        accU[nt][2] = tanh_f(accV[nt][2] + b0 + accU[nt][2]);
        accU[nt][3] = tanh_f(accV[nt][3] + b1 + accU[nt][3]);
    }
    // z = sigmoid(x Wz_x^T + h Wz_h^T + b)
    ZACC(accV);
    gemm(accV, xs, WB + 2 * 16384);
    gemm(accV, hs, WB + 3 * 16384);

    __syncthreads();    // all gemm reads of hs done before in-place update
    #pragma unroll
    for (int nt = 0; nt < 4; nt++) {
        int col = warpn * 32 + nt * 8 + t4 * 2;
        float b0 = bih[128 + col] + bhh[128 + col];
        float b1 = bih[129 + col] + bhh[129 + col];
        uint32_t h0a = hs + arow + col * 4;
        uint32_t h1a = h0a + 8 * APAD * 4;
        float2 ho0 = lds2(h0a), ho1 = lds2(h1a);
        float z0 = sigmoid_f(accV[nt][0] + b0);
        float z1 = sigmoid_f(accV[nt][1] + b1);
        float z2 = sigmoid_f(accV[nt][2] + b0);
        float z3 = sigmoid_f(accV[nt][3] + b1);
        float2 o0, o1;
        o0.x = fmaf(z0, ho0.x - accU[nt][0], accU[nt][0]);
        o0.y = fmaf(z1, ho0.y - accU[nt][1], accU[nt][1]);
        o1.x = fmaf(z2, ho1.x - accU[nt][2], accU[nt][2]);
        o1.y = fmaf(z3, ho1.y - accU[nt][3], accU[nt][3]);
        sts2(h0a, o0);
        sts2(h1a, o1);
    }
    __syncthreads();
    #undef ZACC
}

// ================= SIMT 128x128 dense, SMEM->SMEM (+bias, optional relu) =================
// 8 warps x 4 rows/warp; exact fp32 via f32x2.
__device__ __noinline__ void densef(uint32_t src, uint32_t dst,
                                    const float* __restrict__ WT,
                                    const float* __restrict__ bias, int relu) {
    const int tid = threadIdx.x, wid = tid >> 5, lane = tid & 31;
    const int g0 = 2 * lane;
    ull acc[4][2];
    ull b0 = pack2(bias[g0], bias[g0 + 1]);
    ull b1 = pack2(bias[g0 + 64], bias[g0 + 65]);
    #pragma unroll
    for (int r = 0; r < 4; r++) { acc[r][0] = b0; acc[r][1] = b1; }

    const uint32_t sr = src + (uint32_t)(wid * 4) * (APAD * 4);
    #pragma unroll 1
    for (int k4 = 0; k4 < 32; k4++) {
        float4 a4[4];
        #pragma unroll
        for (int r = 0; r < 4; r++)
            a4[r] = lds4(sr + (uint32_t)(r * APAD + k4 * 4) * 4);
        #pragma unroll
        for (int c = 0; c < 4; c++) {
            const float* wr = WT + (k4 * 4 + c) * HD + g0;
            ull w0 = *reinterpret_cast<const ull*>(wr);
            ull w1 = *reinterpret_cast<const ull*>(wr + 64);
            #pragma unroll
            for (int r = 0; r < 4; r++) {
                float av = (c == 0) ? a4[r].x : (c == 1) ? a4[r].y
                         : (c == 2) ? a4[r].z : a4[r].w;
                ull as = splat2(av);
                FMA2(acc[r][0], as, w0);
                FMA2(acc[r][1], as, w1);
            }
        }
    }
    __syncwarp();       // in-place safety (warps own disjoint rows)
    #pragma unroll
    for (int r = 0; r < 4; r++) {
        #pragma unroll
        for (int m = 0; m < 2; m++) {
            float v0, v1;
            unpack2(acc[r][m], v0, v1);
            if (relu) { v0 = fmaxf(v0, 0.0f); v1 = fmaxf(v1, 0.0f); }
            sts2(dst + (uint32_t)((wid * 4 + r) * APAD + g0 + 64 * m) * 4,
                 make_float2(v0, v1));
        }
    }
    __syncthreads();
}

// ================= fused whole-network kernel =================
__global__ void __launch_bounds__(256, 2)
k_net(const float* __restrict__ x_true, float* __restrict__ out,
      const float* __restrict__ Wemb, const float* __restrict__ bemb,
      const float* __restrict__ enc_bih, const float* __restrict__ enc_bhh,
      const float* __restrict__ enc_bt, const float* __restrict__ dec_bin,
      const float* __restrict__ dec_bih, const float* __restrict__ dec_bhh,
      const float* __restrict__ Wout, const float* __restrict__ bout) {
    extern __shared__ float sm[];
    const uint32_t sb = smem_u32(sm);
    const uint32_t he0 = sb;
    const uint32_t he1 = sb + ROWS * APAD * 4;
    const uint32_t he2 = sb + 2 * ROWS * APAD * 4;
    const uint32_t xe  = sb + 3 * ROWS * APAD * 4;
    const int tid = threadIdx.x;
    const int row0 = blockIdx.x * ROWS;

    for (int i = tid; i < 3 * ROWS * APAD; i += 256) sm[i] = 0.0f;
    __syncthreads();

    // ---- encoder: steps t = 1..T-2 (step 0 discarded per reference) ----
    #pragma unroll 1
    for (int t = 1; t <= NT - 2; t++) {
        #pragma unroll 1
        for (int i = tid; i < ROWS * HD; i += 256) {
            int r = i >> 7, c = i & 127;
            float2 xp = *reinterpret_cast<const float2*>(
                x_true + ((size_t)(row0 + r) * NT + t) * 2);
            float v = fmaf(xp.x, Wemb[2 * c], fmaf(xp.y, Wemb[2 * c + 1], bemb[c]));
            sm[3 * ROWS * APAD + r * APAD + c] = fmaxf(v, 0.0f);
        }
        __syncthreads();
        cellf(xe,  he0, g_wB[0], enc_bih,          enc_bhh);
        cellf(he0, he1, g_wB[1], enc_bih + G3,     enc_bhh + G3);
        cellf(he1, he2, g_wB[2], enc_bih + 2 * G3, enc_bhh + 2 * G3);
    }

    // rep = h_top @ enc_Wt^T + bt  -> xe
    densef(he2, xe, &g_wt2[0][0][0], enc_bt, 0);

    for (int i = tid; i < 3 * ROWS * APAD; i += 256) sm[i] = 0.0f;
    __syncthreads();

    // ---- decoder: 12 steps; carry = top hidden (rep for step 0, in xe) ----
    #pragma unroll 1
    for (int i = 0; i < NT; i++) {
        densef(i == 0 ? xe : he2, xe, &g_wt2[1][0][0], dec_bin, 1);
        cellf(xe,  he0, g_wB[3], dec_bih,          dec_bhh);
        cellf(he0, he1, g_wB[4], dec_bih + G3,     dec_bhh + G3);
        cellf(he1, he2, g_wB[5], dec_bih + 2 * G3, dec_bhh + 2 * G3);

        // output head: y = h_top @ Wout^T + bout
        {
            int wid = tid >> 5, lane = tid & 31;
            float4 w0 = *reinterpret_cast<const float4*>(Wout + lane * 4);
            float4 w1 = *reinterpret_cast<const float4*>(Wout + HD + lane * 4);
            #pragma unroll
            for (int rr = 0; rr < 4; rr++) {
                int r = wid * 4 + rr;
                float4 hv = *reinterpret_cast<const float4*>(
                    sm + 2 * ROWS * APAD + r * APAD + lane * 4);
                float d0 = hv.x * w0.x + hv.y * w0.y + hv.z * w0.z + hv.w * w0.w;
                float d1 = hv.x * w1.x + hv.y * w1.y + hv.z * w1.z + hv.w * w1.w;
                #pragma unroll
                for (int s = 16; s; s >>= 1) {
                    d0 += __shfl_xor_sync(0xFFFFFFFFu, d0, s);
                    d1 += __shfl_xor_sync(0xFFFFFFFFu, d1, s);
                }
                if (lane == 0) {
                    float* o = out + ((size_t)(row0 + r) * NT + i) * 2;
                    o[0] = d0 + bout[0];
                    o[1] = d1 + bout[1];
                }
            }
        }
    }
}

extern "C" void kernel_launch(void* const* d_in, const int* in_sizes, int n_in,
                              void* d_out, int out_size) {
    const float* x_true   = (const float*)d_in[0];
    const float* enc_Wemb = (const float*)d_in[1];
    const float* enc_bemb = (const float*)d_in[2];
    const float* enc_Wih  = (const float*)d_in[3];
    const float* enc_Whh  = (const float*)d_in[4];
    const float* enc_bih  = (const float*)d_in[5];
    const float* enc_bhh  = (const float*)d_in[6];
    const float* enc_Wt   = (const float*)d_in[7];
    const float* enc_bt   = (const float*)d_in[8];
    const float* dec_Win  = (const float*)d_in[9];
    const float* dec_bin  = (const float*)d_in[10];
    const float* dec_Wih  = (const float*)d_in[11];
    const float* dec_Whh  = (const float*)d_in[12];
    const float* dec_bih  = (const float*)d_in[13];
    const float* dec_bhh  = (const float*)d_in[14];
    const float* dec_Wout = (const float*)d_in[15];
    const float* dec_bout = (const float*)d_in[16];
    float* out = (float*)d_out;

    cudaFuncSetAttribute(k_net, cudaFuncAttributeMaxDynamicSharedMemorySize, SMEM_NET);

    k_prep_all<<<6 * 192, 256>>>(enc_Wih, enc_Whh, dec_Wih, dec_Whh);
    k_tr2_all<<<128, 256>>>(enc_Wt, dec_Win);
    k_net<<<NB / ROWS, 256, SMEM_NET>>>(x_true, out, enc_Wemb, enc_bemb,
                                        enc_bih, enc_bhh, enc_bt, dec_bin,
                                        dec_bih, dec_bhh, dec_Wout, dec_bout);
}